// round 16
// baseline (speedup 1.0000x reference)
#include <cuda_runtime.h>
#include <cstdint>

// ---------------- problem constants ----------------
#define BB   2
#define VV   4
#define FD   128
#define ED   128
#define NHN  7
#define NN6  196608
#define NN5  49152
#define NN4  12288
#define PFN  32768
#define PP5  8192
#define PP4  2048
#define OO5  4
#define OO4  16

#define THREADS 256
#define TILE_M  64
#define GRID    304                  // 152 SMs x 2 persistent CTAs

#define AP 132                       // sA pitch (floats)
#define WP 132                       // sW pitch (floats, n-major W^T)

// ---- smem layout (float/word offsets) ----
#define SA_O 0
#define SA_FLOATS (TILE_M * AP)          // 8448
#define SW_O SA_FLOATS
#define SW_FLOATS (ED * WP)              // 16896
#define MET_O (SW_O + SW_FLOATS)         // 25344
#define MET_W 1104                       // words per meta stage
// within a meta stage:
#define IDX6_O 0                         // 64 ints
#define NP5_O  64                        // 112 ints  [16 grp][7]
#define NP4_O  176                       // 28 ints   [4 grp][7] (+pad)
#define W5_O   208                       // 448 floats [64 pt][7]
#define W4_O   656                       // 448 floats [4 grp][16 o][7]
#define SMEM_FLOATS (MET_O + 2 * MET_W)  // 27552
#define SMEM_TOTAL (SMEM_FLOATS * 4)     // 110208 B -> 2 CTAs/SM

typedef unsigned long long u64;

// scratch (device globals allowed)
__device__ float g_w5[BB * PP5 * OO5 * NHN];
__device__ float g_w4[BB * PP4 * OO4 * NHN];
__device__ float g_Wt[ED * FD];      // W transposed (n-major), rna-tf32 rounded

// ---------------- PTX helpers (baseline sm_80+ only) ----------------
__device__ __forceinline__ uint32_t f2tf32(float f) {
    uint32_t r; asm("cvt.rna.tf32.f32 %0, %1;" : "=r"(r) : "f"(f)); return r;
}
__device__ __forceinline__ u64 pack2(float s) {
    u64 r; unsigned ui = __float_as_uint(s);
    asm("mov.b64 %0, {%1, %1};" : "=l"(r) : "r"(ui));
    return r;
}
__device__ __forceinline__ u64 fma2(u64 a, u64 b, u64 c) {
    u64 d; asm("fma.rn.f32x2 %0, %1, %2, %3;" : "=l"(d) : "l"(a), "l"(b), "l"(c)); return d;
}
__device__ __forceinline__ void mma_tf32(float* c, const uint32_t* a,
                                         uint32_t b0, uint32_t b1) {
    asm volatile(
        "mma.sync.aligned.m16n8k8.row.col.f32.tf32.tf32.f32 "
        "{%0,%1,%2,%3}, {%4,%5,%6,%7}, {%8,%9}, {%0,%1,%2,%3};"
        : "+f"(c[0]), "+f"(c[1]), "+f"(c[2]), "+f"(c[3])
        : "r"(a[0]), "r"(a[1]), "r"(a[2]), "r"(a[3]), "r"(b0), "r"(b1));
}
__device__ __forceinline__ void ldsm4(uint32_t* r, uint32_t addr) {
    asm volatile("ldmatrix.sync.aligned.m8n8.x4.shared.b16 {%0,%1,%2,%3}, [%4];"
                 : "=r"(r[0]), "=r"(r[1]), "=r"(r[2]), "=r"(r[3]) : "r"(addr));
}
__device__ __forceinline__ void cp16(uint32_t dst, const void* src) {
    asm volatile("cp.async.cg.shared.global [%0], [%1], 16;" :: "r"(dst), "l"(src) : "memory");
}
__device__ __forceinline__ void stcs2(float* p, float x, float y) {
    asm volatile("st.global.cs.v2.f32 [%0], {%1, %2};" :: "l"(p), "f"(x), "f"(y) : "memory");
}
#define CP_COMMIT() asm volatile("cp.async.commit_group;" ::: "memory")
#define CP_WAIT0()  asm volatile("cp.async.wait_group 0;" ::: "memory")

// normalized inverse-distance weights via prefix/suffix products: 1 rcp total.
__device__ __forceinline__ void norm_weights(const float* rd, const float* mm, float* wout) {
    float d[NHN]; bool msk[NHN];
#pragma unroll
    for (int n = 0; n < NHN; n++) {
        msk[n] = (mm[n] != 0.0f);
        d[n] = msk[n] ? 1.0f : (1e-20f + rd[n]);
    }
    float pre[NHN], suf[NHN];
    pre[0] = 1.f;
#pragma unroll
    for (int n = 1; n < NHN; n++) pre[n] = pre[n - 1] * d[n - 1];
    suf[NHN - 1] = 1.f;
#pragma unroll
    for (int n = NHN - 2; n >= 0; n--) suf[n] = suf[n + 1] * d[n + 1];
    float s = 0.f; float t[NHN];
#pragma unroll
    for (int n = 0; n < NHN; n++) {
        t[n] = msk[n] ? 0.f : pre[n] * suf[n];
        s += t[n];
    }
    float inv = __frcp_rn(s);
#pragma unroll
    for (int n = 0; n < NHN; n++) wout[n] = t[n] * inv;
}

// ---------------- pre-pass: interp weights + W^T tf32(rna) ----------------
__global__ void weights_kernel(const float* __restrict__ rd5, const float* __restrict__ m5,
                               const float* __restrict__ rd4, const float* __restrict__ m4,
                               const float* __restrict__ Wm)
{
    const int T5 = BB * PP5 * OO5;
    const int T4 = BB * PP4 * OO4;
    int t = blockIdx.x * blockDim.x + threadIdx.x;
    if (t < T5) {
        int pcb = t / OO5;
        float w[NHN];
        norm_weights(rd5 + (size_t)t * NHN, m5 + (size_t)pcb * NHN, w);
#pragma unroll
        for (int n = 0; n < NHN; n++) g_w5[(size_t)t * NHN + n] = w[n];
    } else if (t < T5 + T4) {
        int tt = t - T5;
        int pcb = tt / OO4;
        float w[NHN];
        norm_weights(rd4 + (size_t)tt * NHN, m4 + (size_t)pcb * NHN, w);
#pragma unroll
        for (int n = 0; n < NHN; n++) g_w4[(size_t)tt * NHN + n] = w[n];
    } else if (t < T5 + T4 + FD * ED) {
        int i = t - (T5 + T4);
        int k = i >> 7, n = i & 127;
        ((uint32_t*)g_Wt)[n * FD + k] = f2tf32(Wm[i]);    // transpose to n-major
    }
}

// ---------------- persistent fused kernel (warp-specialized) ----------------
__global__ __launch_bounds__(THREADS, 2)
void embed_kernel(const float* __restrict__ table6, const float* __restrict__ table5,
                  const float* __restrict__ table4,
                  const float* __restrict__ bias,
                  const int* __restrict__ var_idx, const int* __restrict__ idx6,
                  const int* __restrict__ nh5, const int* __restrict__ nh4,
                  float* __restrict__ out)
{
    extern __shared__ float smem[];
    float* sA = smem + SA_O;
    const uint32_t sm_u = (uint32_t)__cvta_generic_to_shared(smem);

    const int tid  = threadIdx.x;
    const int lane = tid & 31;
    const int w    = tid >> 5;           // 0..7; 0-3 GEMM, 4-7 interp
    const int gid  = lane >> 2;
    const int tid4 = lane & 3;

    // ---- dedup bookkeeping ----
    uint32_t vrpack = 0;
#pragma unroll
    for (int j = 0; j < BB * VV; j++) vrpack |= ((uint32_t)var_idx[j] & 15u) << (4 * j);
    uint32_t uniqpack = 0; int U = 0;
#pragma unroll
    for (int bv = 0; bv < BB * VV; bv++) {
        int bb = bv >> 2;
        uint32_t vi = (vrpack >> (4 * bv)) & 15u;
        bool dup = false;
#pragma unroll
        for (int j = 0; j < BB * VV; j++)
            if (j >= bb * 4 && j < bv && ((vrpack >> (4 * j)) & 15u) == vi) dup = true;
        if (!dup) { uniqpack |= (uint32_t)bv << (4 * U); U++; }
    }
    const int total = U << 9;            // 512 tiles per unique (b,vi)

    const ulonglong2 bias2 = ((const ulonglong2*)bias)[lane];

    auto issue_meta = [&](int t, int buf) {
        const int tl = t & 511;
        const int bv = (uniqpack >> (4 * (t >> 9))) & 15;
        const int b  = bv >> 2;
        const uint32_t base = sm_u + (uint32_t)(MET_O + buf * MET_W) * 4u;
        const int* i6s  = idx6 + b * PFN + tl * 64;
        const int* n5s  = nh5 + ((size_t)b * PP5 + tl * 16) * NHN;
        const int* n4s  = nh4 + ((size_t)b * PP4 + tl * 4) * NHN;
        const float* w5s = g_w5 + ((size_t)b * PP5 + tl * 16) * (OO5 * NHN);
        const float* w4s = g_w4 + ((size_t)b * PP4 + tl * 4) * (OO4 * NHN);
        for (int c = tid; c < 275; c += THREADS) {
            if (c < 16)        cp16(base + (IDX6_O + c * 4) * 4u, i6s + c * 4);
            else if (c < 44)   cp16(base + (NP5_O + (c - 16) * 4) * 4u, n5s + (c - 16) * 4);
            else if (c < 51)   cp16(base + (NP4_O + (c - 44) * 4) * 4u, n4s + (c - 44) * 4);
            else if (c < 163)  cp16(base + (W5_O + (c - 51) * 4) * 4u, w5s + (c - 51) * 4);
            else               cp16(base + (W4_O + (c - 163) * 4) * 4u, w4s + (c - 163) * 4);
        }
    };
    auto issue_A = [&](int t, int buf) {
        const int bv = (uniqpack >> (4 * (t >> 9))) & 15;
        const uint32_t vi = (vrpack >> (4 * bv)) & 15u;
        const float* tb6 = table6 + (size_t)vi * ((size_t)NN6 * FD);
        const int* i6m = (const int*)(smem + MET_O + buf * MET_W + IDX6_O);
#pragma unroll
        for (int j = 0; j < 8; j++) {
            int rl = w * 8 + j;
            int row = i6m[rl];
            cp16(sm_u + (uint32_t)(SA_O + rl * AP) * 4u + (uint32_t)lane * 16u,
                 tb6 + (size_t)row * FD + lane * 4);
        }
    };

    // ---- prologue: W^T + meta(t0) + meta(t0+G); wait; then A(t0) ----
    int t = blockIdx.x;
#pragma unroll
    for (int i = 0; i < 16; i++) {
        int c = tid + i * THREADS;
        int row = c >> 5, col = c & 31;
        cp16(sm_u + (uint32_t)(SW_O + row * WP) * 4u + (uint32_t)col * 16u,
             g_Wt + (size_t)row * FD + col * 4);
    }
    if (t < total) issue_meta(t, 0);
    if (t + GRID < total) issue_meta(t + GRID, 1);
    CP_COMMIT();
    CP_WAIT0();
    __syncthreads();
    if (t < total) issue_A(t, 0);
    CP_COMMIT();

    // GEMM warps (0-3): 64x32 C tile, NC = w*32
    const int NC = (w & 3) * 32;
    const uint32_t aBase = sm_u + (uint32_t)(((SA_O + (lane & 15) * AP)
                                              + (lane >> 4) * 4) * 4);
    const uint32_t bBase = sm_u + (uint32_t)((SW_O + (NC + lane) * WP) * 4);
    const int iw = w - 4;                // interp warp index 0..3

    int p = 0;
    for (; t < total; t += GRID, p ^= 1) {
        const int tl = t & 511;
        const int bv = (uniqpack >> (4 * (t >> 9))) & 15;
        const int b  = bv >> 2;
        const uint32_t vi = (vrpack >> (4 * bv)) & 15u;
        const float* tb5 = table5 + (size_t)vi * ((size_t)NN5 * FD);
        const float* tb4 = table4 + (size_t)vi * ((size_t)NN4 * FD);
        const float* met = smem + MET_O + p * MET_W;

        CP_WAIT0();          // A(t) landed (+ meta(t+2G) from prev iter)
        __syncthreads();     // sync 1

        float acc[4][4][4];  // GEMM accumulators (warps 0-3)
        u64 aL[16], aH[16];  // interp accumulators (warps 4-7)

        if (w < 4) {
            // ---- GEMM: 64x32 per warp via ldmatrix + mma ----
#pragma unroll
            for (int mi = 0; mi < 4; mi++)
#pragma unroll
                for (int ni = 0; ni < 4; ni++)
#pragma unroll
                    for (int r = 0; r < 4; r++) acc[mi][ni][r] = 0.f;

#pragma unroll
            for (int k0 = 0; k0 < FD; k0 += 8) {
                uint32_t a[4][4], b0[4], b1[4];
                ldsm4(b0, bBase + k0 * 4);
                ldsm4(b1, bBase + k0 * 4 + 16);
#pragma unroll
                for (int mi = 0; mi < 4; mi++)
                    ldsm4(a[mi], aBase + (uint32_t)(mi * 16 * AP * 4) + k0 * 4);
#pragma unroll
                for (int mi = 0; mi < 4; mi++)
#pragma unroll
                    for (int ni = 0; ni < 4; ni++)
                        mma_tf32(acc[mi][ni], a[mi], b0[ni], b1[ni]);
            }
        } else {
            // ---- interp: 16 points (one pc4 group, four pc5 groups) ----
            const int* np5m = (const int*)(met + NP5_O);
            const int* np4m = (const int*)(met + NP4_O);
            const float* w5m = met + W5_O + (iw * 16) * NHN;   // [pt][n]
            const float* w4m = met + W4_O + (iw * 16) * NHN;   // [pt][n]

#pragma unroll
            for (int j = 0; j < 16; j++) { aL[j] = bias2.x; aH[j] = bias2.y; }

            {   // level-4: all 16 points share the pc4 group's rows
                ulonglong2 t4r[NHN];
#pragma unroll
                for (int n = 0; n < NHN; n++)
                    t4r[n] = ((const ulonglong2*)(tb4 + (size_t)np4m[iw * NHN + n] * FD))[lane];
#pragma unroll
                for (int n = 0; n < NHN; n++) {
#pragma unroll
                    for (int j = 0; j < 16; j++) {
                        u64 wn = pack2(w4m[j * NHN + n]);
                        aL[j] = fma2(wn, t4r[n].x, aL[j]);
                        aH[j] = fma2(wn, t4r[n].y, aH[j]);
                    }
                }
            }
            // level-5: 4 groups of 4 points
#pragma unroll
            for (int g = 0; g < 4; g++) {
                ulonglong2 t5r[NHN];
                const int* np = np5m + (iw * 4 + g) * NHN;
#pragma unroll
                for (int n = 0; n < NHN; n++)
                    t5r[n] = ((const ulonglong2*)(tb5 + (size_t)np[n] * FD))[lane];
#pragma unroll
                for (int n = 0; n < NHN; n++) {
#pragma unroll
                    for (int jj = 0; jj < 4; jj++) {
                        int j = g * 4 + jj;
                        u64 wn = pack2(w5m[j * NHN + n]);
                        aL[j] = fma2(wn, t5r[n].x, aL[j]);
                        aH[j] = fma2(wn, t5r[n].y, aH[j]);
                    }
                }
            }
        }
        __syncthreads();     // sync 2: GEMM's sA reads done; interp acc ready

        // ---- interp warps stage results into sA (now dead) ----
        if (w >= 4) {
#pragma unroll
            for (int j = 0; j < 16; j++) {
                ulonglong2 o; o.x = aL[j]; o.y = aH[j];
                *(ulonglong2*)(sA + (size_t)(iw * 16 + j) * AP + lane * 4) = o;
            }
        }
        __syncthreads();     // sync 3

        // ---- meta(t+2G) into buf p (dead now) — covered by epilogue ----
        if (t + 2 * GRID < total) issue_meta(t + 2 * GRID, p);
        CP_COMMIT();

        // ---- epilogue (GEMM warps): C + interp -> gmem for bv and dups ----
        if (w < 4) {
#pragma unroll
            for (int v2 = 0; v2 < VV; v2++) {
                if (((vrpack >> (4 * (b * VV + v2))) & 15u) != vi) continue;
                float* ob = out + (((size_t)(b * VV + v2)) * PFN + (size_t)tl * TILE_M) * ED;
#pragma unroll
                for (int mi = 0; mi < 4; mi++) {
                    const int row0 = mi * 16 + gid;
                    const int row1 = row0 + 8;
#pragma unroll
                    for (int ni = 0; ni < 4; ni++) {
                        const int col = NC + ni * 8 + 2 * tid4;
                        float2 i0 = *(const float2*)(sA + (size_t)row0 * AP + col);
                        float2 i1 = *(const float2*)(sA + (size_t)row1 * AP + col);
                        stcs2(ob + (size_t)row0 * ED + col,
                              acc[mi][ni][0] + i0.x, acc[mi][ni][1] + i0.y);
                        stcs2(ob + (size_t)row1 * ED + col,
                              acc[mi][ni][2] + i1.x, acc[mi][ni][3] + i1.y);
                    }
                }
            }
        }
        __syncthreads();     // sync 4: sA reads done before next A staging

        // ---- prefetch: A(t+G) from meta buf p^1 ----
        if (t + GRID < total) issue_A(t + GRID, p ^ 1);
        CP_COMMIT();
    }
}

// ---------------- launch ----------------
extern "C" void kernel_launch(void* const* d_in, const int* in_sizes, int n_in,
                              void* d_out, int out_size)
{
    const float* table6 = (const float*)d_in[0];
    const float* table5 = (const float*)d_in[1];
    const float* table4 = (const float*)d_in[2];
    const float* Wm     = (const float*)d_in[3];
    const float* bias   = (const float*)d_in[4];
    const float* rd5    = (const float*)d_in[5];
    const float* rd4    = (const float*)d_in[6];
    const float* m5     = (const float*)d_in[7];
    const float* m4     = (const float*)d_in[8];
    const int*   vidx   = (const int*)d_in[9];
    const int*   idx6   = (const int*)d_in[10];
    const int*   nh5    = (const int*)d_in[11];
    const int*   nh4    = (const int*)d_in[12];
    float* out = (float*)d_out;

    {
        int total = BB * PP5 * OO5 + BB * PP4 * OO4 + FD * ED;
        weights_kernel<<<(total + 255) / 256, 256>>>(rd5, m5, rd4, m4, Wm);
    }
    {
        cudaFuncSetAttribute(embed_kernel,
                             cudaFuncAttributeMaxDynamicSharedMemorySize, SMEM_TOTAL);
        embed_kernel<<<GRID, THREADS, SMEM_TOTAL>>>(table6, table5, table4, bias,
                                                    vidx, idx6, nh5, nh4, out);
    }
}

// round 17
// speedup vs baseline: 1.1749x; 1.1749x over previous
#include <cuda_runtime.h>
#include <cstdint>

// ---------------- problem constants ----------------
#define BB   2
#define VV   4
#define FD   128
#define ED   128
#define NHN  7
#define NN6  196608
#define NN5  49152
#define NN4  12288
#define PFN  32768
#define PP5  8192
#define PP4  2048
#define OO5  4
#define OO4  16

#define THREADS 256
#define TILE_M  64
#define GRID    304                  // 152 SMs x 2 persistent CTAs

#define AP 132                       // sA pitch (floats)
#define WP 132                       // sW pitch (floats, n-major W^T)

// ---- smem layout (float/word offsets) ----
#define SA_O 0
#define SA_FLOATS (TILE_M * AP)          // 8448
#define SW_O SA_FLOATS
#define SW_FLOATS (ED * WP)              // 16896
#define MET_O (SW_O + SW_FLOATS)         // 25344
#define MET_W 1104                       // words per meta stage
// within a meta stage:
#define IDX6_O 0                         // 64 ints
#define NP5_O  64                        // 112 ints  [16 grp][7]
#define NP4_O  176                       // 28 ints   [4 grp][7] (+pad)
#define W5_O   208                       // 448 floats [16 grp][4 o][7]
#define W4_O   656                       // 448 floats [4 grp][16 o][7]
#define SMEM_FLOATS (MET_O + 2 * MET_W)  // 27552
#define SMEM_TOTAL (SMEM_FLOATS * 4)     // 110208 B -> 2 CTAs/SM

typedef unsigned long long u64;

// scratch (device globals allowed)
__device__ float g_w5[BB * PP5 * OO5 * NHN];
__device__ float g_w4[BB * PP4 * OO4 * NHN];
__device__ float g_Wt[ED * FD];      // W transposed (n-major), rna-tf32 rounded

// ---------------- PTX helpers (baseline sm_80+ only) ----------------
__device__ __forceinline__ uint32_t f2tf32(float f) {
    uint32_t r; asm("cvt.rna.tf32.f32 %0, %1;" : "=r"(r) : "f"(f)); return r;
}
__device__ __forceinline__ u64 pack2(float s) {
    u64 r; unsigned ui = __float_as_uint(s);
    asm("mov.b64 %0, {%1, %1};" : "=l"(r) : "r"(ui));
    return r;
}
__device__ __forceinline__ u64 fma2(u64 a, u64 b, u64 c) {
    u64 d; asm("fma.rn.f32x2 %0, %1, %2, %3;" : "=l"(d) : "l"(a), "l"(b), "l"(c)); return d;
}
__device__ __forceinline__ void mma_tf32(float* c, const uint32_t* a,
                                         uint32_t b0, uint32_t b1) {
    asm volatile(
        "mma.sync.aligned.m16n8k8.row.col.f32.tf32.tf32.f32 "
        "{%0,%1,%2,%3}, {%4,%5,%6,%7}, {%8,%9}, {%0,%1,%2,%3};"
        : "+f"(c[0]), "+f"(c[1]), "+f"(c[2]), "+f"(c[3])
        : "r"(a[0]), "r"(a[1]), "r"(a[2]), "r"(a[3]), "r"(b0), "r"(b1));
}
__device__ __forceinline__ void ldsm4(uint32_t* r, uint32_t addr) {
    asm volatile("ldmatrix.sync.aligned.m8n8.x4.shared.b16 {%0,%1,%2,%3}, [%4];"
                 : "=r"(r[0]), "=r"(r[1]), "=r"(r[2]), "=r"(r[3]) : "r"(addr));
}
__device__ __forceinline__ void cp16(uint32_t dst, const void* src) {
    asm volatile("cp.async.cg.shared.global [%0], [%1], 16;" :: "r"(dst), "l"(src) : "memory");
}
__device__ __forceinline__ void stcs2(float* p, float x, float y) {
    asm volatile("st.global.cs.v2.f32 [%0], {%1, %2};" :: "l"(p), "f"(x), "f"(y) : "memory");
}
#define CP_COMMIT() asm volatile("cp.async.commit_group;" ::: "memory")
#define CP_WAIT0()  asm volatile("cp.async.wait_group 0;" ::: "memory")

// normalized inverse-distance weights via prefix/suffix products: 1 rcp total.
__device__ __forceinline__ void norm_weights(const float* rd, const float* mm, float* wout) {
    float d[NHN]; bool msk[NHN];
#pragma unroll
    for (int n = 0; n < NHN; n++) {
        msk[n] = (mm[n] != 0.0f);
        d[n] = msk[n] ? 1.0f : (1e-20f + rd[n]);
    }
    float pre[NHN], suf[NHN];
    pre[0] = 1.f;
#pragma unroll
    for (int n = 1; n < NHN; n++) pre[n] = pre[n - 1] * d[n - 1];
    suf[NHN - 1] = 1.f;
#pragma unroll
    for (int n = NHN - 2; n >= 0; n--) suf[n] = suf[n + 1] * d[n + 1];
    float s = 0.f; float t[NHN];
#pragma unroll
    for (int n = 0; n < NHN; n++) {
        t[n] = msk[n] ? 0.f : pre[n] * suf[n];
        s += t[n];
    }
    float inv = __frcp_rn(s);
#pragma unroll
    for (int n = 0; n < NHN; n++) wout[n] = t[n] * inv;
}

// ---------------- pre-pass: interp weights + W^T tf32(rna) ----------------
__global__ void weights_kernel(const float* __restrict__ rd5, const float* __restrict__ m5,
                               const float* __restrict__ rd4, const float* __restrict__ m4,
                               const float* __restrict__ Wm)
{
    const int T5 = BB * PP5 * OO5;
    const int T4 = BB * PP4 * OO4;
    int t = blockIdx.x * blockDim.x + threadIdx.x;
    if (t < T5) {
        int pcb = t / OO5;
        float w[NHN];
        norm_weights(rd5 + (size_t)t * NHN, m5 + (size_t)pcb * NHN, w);
#pragma unroll
        for (int n = 0; n < NHN; n++) g_w5[(size_t)t * NHN + n] = w[n];
    } else if (t < T5 + T4) {
        int tt = t - T5;
        int pcb = tt / OO4;
        float w[NHN];
        norm_weights(rd4 + (size_t)tt * NHN, m4 + (size_t)pcb * NHN, w);
#pragma unroll
        for (int n = 0; n < NHN; n++) g_w4[(size_t)tt * NHN + n] = w[n];
    } else if (t < T5 + T4 + FD * ED) {
        int i = t - (T5 + T4);
        int k = i >> 7, n = i & 127;
        ((uint32_t*)g_Wt)[n * FD + k] = f2tf32(Wm[i]);    // transpose to n-major
    }
}

// ---------------- persistent fused kernel ----------------
__global__ __launch_bounds__(THREADS, 2)
void embed_kernel(const float* __restrict__ table6, const float* __restrict__ table5,
                  const float* __restrict__ table4,
                  const float* __restrict__ bias,
                  const int* __restrict__ var_idx, const int* __restrict__ idx6,
                  const int* __restrict__ nh5, const int* __restrict__ nh4,
                  float* __restrict__ out)
{
    extern __shared__ float smem[];
    float* sA = smem + SA_O;
    const uint32_t sm_u = (uint32_t)__cvta_generic_to_shared(smem);

    const int tid  = threadIdx.x;
    const int lane = tid & 31;
    const int w    = tid >> 5;           // 0..7
    const int gid  = lane >> 2;
    const int tid4 = lane & 3;

    // ---- dedup bookkeeping (uniform, packed in 2 regs) ----
    uint32_t vrpack = 0;
#pragma unroll
    for (int j = 0; j < BB * VV; j++) vrpack |= ((uint32_t)var_idx[j] & 15u) << (4 * j);
    uint32_t uniqpack = 0; int U = 0;
#pragma unroll
    for (int bv = 0; bv < BB * VV; bv++) {
        int bb = bv >> 2;
        uint32_t vi = (vrpack >> (4 * bv)) & 15u;
        bool dup = false;
#pragma unroll
        for (int j = 0; j < BB * VV; j++)
            if (j >= bb * 4 && j < bv && ((vrpack >> (4 * j)) & 15u) == vi) dup = true;
        if (!dup) { uniqpack |= (uint32_t)bv << (4 * U); U++; }
    }
    const int total = U << 9;            // 512 tiles per unique (b,vi)

    const ulonglong2 bias2 = ((const ulonglong2*)bias)[lane];

    auto issue_meta = [&](int t, int buf) {
        const int tl = t & 511;
        const int bv = (uniqpack >> (4 * (t >> 9))) & 15;
        const int b  = bv >> 2;
        const uint32_t base = sm_u + (uint32_t)(MET_O + buf * MET_W) * 4u;
        const int* i6s  = idx6 + b * PFN + tl * 64;
        const int* n5s  = nh5 + ((size_t)b * PP5 + tl * 16) * NHN;
        const int* n4s  = nh4 + ((size_t)b * PP4 + tl * 4) * NHN;
        const float* w5s = g_w5 + ((size_t)b * PP5 + tl * 16) * (OO5 * NHN);
        const float* w4s = g_w4 + ((size_t)b * PP4 + tl * 4) * (OO4 * NHN);
        for (int c = tid; c < 275; c += THREADS) {
            if (c < 16)        cp16(base + (IDX6_O + c * 4) * 4u, i6s + c * 4);
            else if (c < 44)   cp16(base + (NP5_O + (c - 16) * 4) * 4u, n5s + (c - 16) * 4);
            else if (c < 51)   cp16(base + (NP4_O + (c - 44) * 4) * 4u, n4s + (c - 44) * 4);
            else if (c < 163)  cp16(base + (W5_O + (c - 51) * 4) * 4u, w5s + (c - 51) * 4);
            else               cp16(base + (W4_O + (c - 163) * 4) * 4u, w4s + (c - 163) * 4);
        }
    };
    auto issue_A = [&](int t, int buf) {
        const int bv = (uniqpack >> (4 * (t >> 9))) & 15;
        const uint32_t vi = (vrpack >> (4 * bv)) & 15u;
        const float* tb6 = table6 + (size_t)vi * ((size_t)NN6 * FD);
        const int* i6m = (const int*)(smem + MET_O + buf * MET_W + IDX6_O);
#pragma unroll
        for (int j = 0; j < 8; j++) {
            int rl = w * 8 + j;
            int row = i6m[rl];
            cp16(sm_u + (uint32_t)(SA_O + rl * AP) * 4u + (uint32_t)lane * 16u,
                 tb6 + (size_t)row * FD + lane * 4);
        }
    };

    // ---- prologue: W^T + meta(t0) + meta(t0+G); wait; then A(t0) ----
    int t = blockIdx.x;
#pragma unroll
    for (int i = 0; i < 16; i++) {
        int c = tid + i * THREADS;
        int row = c >> 5, col = c & 31;
        cp16(sm_u + (uint32_t)(SW_O + row * WP) * 4u + (uint32_t)col * 16u,
             g_Wt + (size_t)row * FD + col * 4);
    }
    if (t < total) issue_meta(t, 0);
    if (t + GRID < total) issue_meta(t + GRID, 1);
    CP_COMMIT();
    CP_WAIT0();
    __syncthreads();
    if (t < total) issue_A(t, 0);
    CP_COMMIT();

    const int mw = w & 1, nw = w >> 1;
    const int MR = mw * 32, NC = nw * 32;

    // ldmatrix address bases (fixed per thread)
    const uint32_t aBase = sm_u + (uint32_t)(((SA_O + (MR + (lane & 15)) * AP)
                                              + (lane >> 4) * 4) * 4);
    const uint32_t bBase = sm_u + (uint32_t)((SW_O + (NC + lane) * WP) * 4);

    int p = 0;
    for (; t < total; t += GRID, p ^= 1) {
        const int tl = t & 511;
        const int bv = (uniqpack >> (4 * (t >> 9))) & 15;
        const int b  = bv >> 2;
        const uint32_t vi = (vrpack >> (4 * bv)) & 15u;
        const float* tb5 = table5 + (size_t)vi * ((size_t)NN5 * FD);
        const float* tb4 = table4 + (size_t)vi * ((size_t)NN4 * FD);
        const float* met = smem + MET_O + p * MET_W;

        // ---- issue ONLY the t4 row loads before GEMM (28 regs held) ----
        const int* np5m = (const int*)(met + NP5_O);
        const int* np4m = (const int*)(met + NP4_O);
        ulonglong2 t4r[NHN];
        {
            const int g4 = w >> 1;
#pragma unroll
            for (int n = 0; n < NHN; n++)
                t4r[n] = ((const ulonglong2*)(tb4 + (size_t)np4m[g4 * NHN + n] * FD))[lane];
        }

        CP_WAIT0();          // A(t) landed (+ meta(t+2G) from prev iter)
        __syncthreads();

        // ---- GEMM via ldmatrix + mma: 32x32 per warp ----
        float acc[2][4][4];
#pragma unroll
        for (int mi = 0; mi < 2; mi++)
#pragma unroll
            for (int ni = 0; ni < 4; ni++)
#pragma unroll
                for (int r = 0; r < 4; r++) acc[mi][ni][r] = 0.f;

#pragma unroll
        for (int k0 = 0; k0 < FD; k0 += 8) {
            uint32_t a0[4], a1[4], b0[4], b1[4];
            ldsm4(a0, aBase + k0 * 4);
            ldsm4(a1, aBase + 16 * AP * 4 + k0 * 4);
            ldsm4(b0, bBase + k0 * 4);
            ldsm4(b1, bBase + k0 * 4 + 16);
#pragma unroll
            for (int ni = 0; ni < 4; ni++) {
                mma_tf32(acc[0][ni], a0, b0[ni], b1[ni]);
                mma_tf32(acc[1][ni], a1, b0[ni], b1[ni]);
            }
        }
        __syncthreads();     // sA reads done

        // ---- interpolation: staged load batches, each hidden under prior fma ----
        u64 aL[8], aH[8];
        {
            const float* w5m = met + W5_O;
            const float* w4m = met + W4_O + (w >> 1) * (OO4 * NHN) + (w & 1) * 8 * NHN;
#pragma unroll
            for (int pt = 0; pt < 8; pt++) { aL[pt] = bias2.x; aH[pt] = bias2.y; }

            // issue t5a loads now (latency hidden by level-4 fma below)
            ulonglong2 t5a[NHN];
#pragma unroll
            for (int n = 0; n < NHN; n++)
                t5a[n] = ((const ulonglong2*)(tb5 + (size_t)np5m[(2 * w) * NHN + n] * FD))[lane];

            // level-4: all 8 points share rows (consumes t4r)
#pragma unroll
            for (int n = 0; n < NHN; n++) {
#pragma unroll
                for (int pt = 0; pt < 8; pt++) {
                    u64 wn = pack2(w4m[pt * NHN + n]);
                    aL[pt] = fma2(wn, t4r[n].x, aL[pt]);
                    aH[pt] = fma2(wn, t4r[n].y, aH[pt]);
                }
            }

            // issue t5b loads now (latency hidden by level-5a fma below)
            ulonglong2 t5b[NHN];
#pragma unroll
            for (int n = 0; n < NHN; n++)
                t5b[n] = ((const ulonglong2*)(tb5 + (size_t)np5m[(2 * w + 1) * NHN + n] * FD))[lane];

            // level-5 group A: points 0..3 (consumes t5a)
#pragma unroll
            for (int n = 0; n < NHN; n++) {
#pragma unroll
                for (int pt = 0; pt < 4; pt++) {
                    u64 wn = pack2(w5m[(w * 8 + pt) * NHN + n]);
                    aL[pt] = fma2(wn, t5a[n].x, aL[pt]);
                    aH[pt] = fma2(wn, t5a[n].y, aH[pt]);
                }
            }
            // level-5 group B: points 4..7 (consumes t5b)
#pragma unroll
            for (int n = 0; n < NHN; n++) {
#pragma unroll
                for (int pt = 0; pt < 4; pt++) {
                    u64 wn = pack2(w5m[(w * 8 + 4 + pt) * NHN + n]);
                    aL[4 + pt] = fma2(wn, t5b[n].x, aL[4 + pt]);
                    aH[4 + pt] = fma2(wn, t5b[n].y, aH[4 + pt]);
                }
            }
        }

        // ---- stage interp regs into sA ----
#pragma unroll
        for (int pt = 0; pt < 8; pt++) {
            ulonglong2 o; o.x = aL[pt]; o.y = aH[pt];
            *(ulonglong2*)(sA + (size_t)(w * 8 + pt) * AP + lane * 4) = o;
        }
        __syncthreads();

        // ---- meta(t+2G) into buf p (dead now) — covered by epilogue ----
        if (t + 2 * GRID < total) issue_meta(t + 2 * GRID, p);
        CP_COMMIT();

        // ---- epilogue: C + interp -> gmem (streaming) for bv and dups ----
#pragma unroll
        for (int v2 = 0; v2 < VV; v2++) {
            if (((vrpack >> (4 * (b * VV + v2))) & 15u) != vi) continue;
            float* ob = out + (((size_t)(b * VV + v2)) * PFN + (size_t)tl * TILE_M) * ED;
#pragma unroll
            for (int mi = 0; mi < 2; mi++) {
                const int row0 = MR + mi * 16 + gid;
                const int row1 = row0 + 8;
#pragma unroll
                for (int ni = 0; ni < 4; ni++) {
                    const int col = NC + ni * 8 + 2 * tid4;
                    float2 i0 = *(const float2*)(sA + (size_t)row0 * AP + col);
                    float2 i1 = *(const float2*)(sA + (size_t)row1 * AP + col);
                    stcs2(ob + (size_t)row0 * ED + col,
                          acc[mi][ni][0] + i0.x, acc[mi][ni][1] + i0.y);
                    stcs2(ob + (size_t)row1 * ED + col,
                          acc[mi][ni][2] + i1.x, acc[mi][ni][3] + i1.y);
                }
            }
        }
        __syncthreads();     // sA reads done before next A staging

        // ---- prefetch: A(t+G) from meta buf p^1 ----
        if (t + GRID < total) issue_A(t + GRID, p ^ 1);
        CP_COMMIT();
    }
}

// ---------------- launch ----------------
extern "C" void kernel_launch(void* const* d_in, const int* in_sizes, int n_in,
                              void* d_out, int out_size)
{
    const float* table6 = (const float*)d_in[0];
    const float* table5 = (const float*)d_in[1];
    const float* table4 = (const float*)d_in[2];
    const float* Wm     = (const float*)d_in[3];
    const float* bias   = (const float*)d_in[4];
    const float* rd5    = (const float*)d_in[5];
    const float* rd4    = (const float*)d_in[6];
    const float* m5     = (const float*)d_in[7];
    const float* m4     = (const float*)d_in[8];
    const int*   vidx   = (const int*)d_in[9];
    const int*   idx6   = (const int*)d_in[10];
    const int*   nh5    = (const int*)d_in[11];
    const int*   nh4    = (const int*)d_in[12];
    float* out = (float*)d_out;

    {
        int total = BB * PP5 * OO5 + BB * PP4 * OO4 + FD * ED;
        weights_kernel<<<(total + 255) / 256, 256>>>(rd5, m5, rd4, m4, Wm);
    }
    {
        cudaFuncSetAttribute(embed_kernel,
                             cudaFuncAttributeMaxDynamicSharedMemorySize, SMEM_TOTAL);
        embed_kernel<<<GRID, THREADS, SMEM_TOTAL>>>(table6, table5, table4, bias,
                                                    vidx, idx6, nh5, nh4, out);
    }
}